// round 3
// baseline (speedup 1.0000x reference)
#include <cuda_runtime.h>

// Problem constants (match reference)
#define B_   8
#define NL_  256
#define NP_  16384
#define DL_  10
#define DP_  4
#define DELTA_ 0.01f
#define L_BIND_ 1.0
#define L_MREG_ 0.1

// Device-global accumulators / scratch (no allocations allowed)
__device__ double g_bind;
__device__ double g_denoise;
__device__ double g_mreg;
__device__ double g_msum;
__device__ float  g_ql[B_ * NL_];

__device__ __forceinline__ float warp_sum(float v) {
    #pragma unroll
    for (int o = 16; o > 0; o >>= 1)
        v += __shfl_down_sync(0xffffffffu, v, o);
    return v;
}

__global__ void zero_kernel() {
    g_bind = 0.0; g_denoise = 0.0; g_mreg = 0.0; g_msum = 0.0;
}

// One thread per (b, n): denoise/mreg partials, msum, ligand charge via argmax.
__global__ void small_kernel(const float* __restrict__ pred,
                             const float* __restrict__ targ,
                             const float* __restrict__ scaf,
                             const float* __restrict__ lfeat,
                             const float* __restrict__ mask,
                             const float* __restrict__ lig_tab) {
    int idx = blockIdx.x * blockDim.x + threadIdx.x;   // 0 .. B*NL-1
    float m = mask[idx];

    const float* p = pred + idx * 3;
    const float* t = targ + idx * 3;
    const float* s = scaf + idx * 3;
    float mse = 0.f, md = 0.f;
    #pragma unroll
    for (int d = 0; d < 3; d++) {
        float dp = p[d] - t[d];
        float ds = s[d] - t[d];
        mse = fmaf(dp, dp, mse);   // no amplification on this path; any rounding ok
        md  = fmaf(ds, ds, md);
    }

    // argmax over DL features (first max wins, strict >)
    const float* f = lfeat + idx * DL_;
    int best = 0; float bv = f[0];
    #pragma unroll
    for (int i = 1; i < DL_; i++) {
        float v = f[i];
        if (v > bv) { bv = v; best = i; }
    }
    g_ql[idx] = lig_tab[best];

    float a = warp_sum(mse * m);
    float b = warp_sum(md * m);
    float c = warp_sum(m);
    if ((threadIdx.x & 31) == 0) {
        atomicAdd(&g_denoise, (double)a);
        atomicAdd(&g_mreg,    (double)b);
        atomicAdd(&g_msum,    (double)c);
    }
}

#define TPB 256
#define PROT_PER_THREAD 2
#define PROT_PER_BLOCK (TPB * PROT_PER_THREAD)   // 512

// sum of squares with XLA's rounding: (x0^2 + x1^2) + x2^2, each op rounded
__device__ __forceinline__ float sumsq_xla(float x, float y, float z) {
    return __fadd_rn(__fadd_rn(__fmul_rn(x, x), __fmul_rn(y, y)), __fmul_rn(z, z));
}

// grid: (NP/PROT_PER_BLOCK, B). Ligand tile in shared; each thread owns
// PROT_PER_THREAD protein atoms; inner loop over all 256 ligands.
__global__ void __launch_bounds__(TPB) bind_kernel(
        const float* __restrict__ x0,        // target_coords2 [B,NL,3]
        const float* __restrict__ prot,      // protein_coords [B,NP,3]
        const float* __restrict__ pfeat,     // protein_features [B,NP,DP]
        const float* __restrict__ prot_tab)  // [DP]
{
    __shared__ float sx[NL_], sy[NL_], sz[NL_], sq[NL_], sx2[NL_];
    const int b   = blockIdx.y;
    const int tid = threadIdx.x;

    // Stage ligand tile (TPB == NL: one element per thread)
    {
        const float* c = x0 + (b * NL_ + tid) * 3;
        float x = c[0], y = c[1], z = c[2];
        sx[tid]  = x; sy[tid] = y; sz[tid] = z;
        sx2[tid] = sumsq_xla(x, y, z);       // matches jnp.sum(x*x, -1) rounding
        sq[tid]  = g_ql[b * NL_ + tid];
    }
    __syncthreads();

    float t0 = prot_tab[0], t1 = prot_tab[1], t2 = prot_tab[2], t3 = prot_tab[3];

    float acc = 0.f;
    const int m_base = blockIdx.x * PROT_PER_BLOCK + tid;

    #pragma unroll
    for (int r = 0; r < PROT_PER_THREAD; r++) {
        const int m = m_base + r * TPB;
        const float* c = prot + (b * NP_ + m) * 3;
        float px = c[0], py = c[1], pz = c[2];
        float p2 = sumsq_xla(px, py, pz);

        const float* f = pfeat + (b * NP_ + m) * DP_;
        float f0 = f[0], f1 = f[1], f2 = f[2], f3 = f[3];
        // argmax over 4, first-max-wins
        float qp = t0; float bv = f0;
        if (f1 > bv) { bv = f1; qp = t1; }
        if (f2 > bv) { bv = f2; qp = t2; }
        if (f3 > bv) { bv = f3; qp = t3; }

        float e = 0.f, v = 0.f;
        #pragma unroll 8
        for (int n = 0; n < NL_; n++) {
            // === bit-match XLA fp32 sequence (amplified x12 by vdw) ===
            // gemm k-ascending FMA chain, acc init 0:
            float dot = __fmaf_rn(sz[n], pz,
                        __fmaf_rn(sy[n], py,
                        __fmul_rn(sx[n], px)));
            // (x2 + p2) - (2 * dot), each op rounded, no contraction:
            float d2 = __fsub_rn(__fadd_rn(sx2[n], p2),
                                 __fmul_rn(2.0f, dot));
            d2 = fmaxf(d2, 0.0f);
            float d    = __fadd_rn(__fsqrt_rn(d2), DELTA_);
            float inv  = __frcp_rn(d);                  // == round(1.0/d)
            // integer_pow(inv, 6) via repeated squaring, each mul rounded:
            float inv2 = __fmul_rn(inv,  inv);
            float inv4 = __fmul_rn(inv2, inv2);
            float inv6 = __fmul_rn(inv2, inv4);
            // vdw: round(inv6*inv6) - inv6 (NOT fused):
            float vdw  = __fsub_rn(__fmul_rn(inv6, inv6), inv6);
            v += vdw;
            e = fmaf(sq[n], inv, e);   // elec: tiny magnitude, rounding-free path
        }
        acc = fmaf(qp, e, acc) + v;
    }

    float blk = warp_sum(acc);
    if ((tid & 31) == 0) atomicAdd(&g_bind, (double)blk);
}

__global__ void final_kernel(float* __restrict__ out) {
    double msum = g_msum;
    double val = g_denoise / msum
               + L_BIND_ * (g_bind / (double)B_)
               + L_MREG_ * (g_mreg / msum);
    out[0] = (float)val;
}

extern "C" void kernel_launch(void* const* d_in, const int* in_sizes, int n_in,
                              void* d_out, int out_size) {
    const float* pred     = (const float*)d_in[0];  // predicted_noise   [B,NL,3]
    const float* targ     = (const float*)d_in[1];  // target_coords     [B,NL,3]
    const float* scaf     = (const float*)d_in[2];  // scaffold_coords   [B,NL,3]
    const float* x0       = (const float*)d_in[3];  // target_coords2    [B,NL,3]
    const float* lfeat    = (const float*)d_in[4];  // target_features   [B,NL,DL]
    const float* mask     = (const float*)d_in[5];  // mask              [B,NL]
    const float* prot     = (const float*)d_in[6];  // protein_coords    [B,NP,3]
    const float* pfeat    = (const float*)d_in[7];  // protein_features  [B,NP,DP]
    const float* lig_tab  = (const float*)d_in[8];  // [DL]
    const float* prot_tab = (const float*)d_in[9];  // [DP]
    float* out = (float*)d_out;

    zero_kernel<<<1, 1>>>();
    small_kernel<<<(B_ * NL_) / 256, 256>>>(pred, targ, scaf, lfeat, mask, lig_tab);
    dim3 grid(NP_ / PROT_PER_BLOCK, B_);
    bind_kernel<<<grid, TPB>>>(x0, prot, pfeat, prot_tab);
    final_kernel<<<1, 1>>>(out);
}

// round 5
// speedup vs baseline: 1.6800x; 1.6800x over previous
#include <cuda_runtime.h>

// Problem constants (match reference)
#define B_   8
#define NL_  256
#define NP_  16384
#define DL_  10
#define DP_  4
#define DELTA_ 0.01f
#define L_BIND_ 1.0
#define L_MREG_ 0.1

#define TPB 128            // threads per bind block
#define PPB 128            // protein atoms per bind block
#define NBLOCKS ((NP_ / PPB) * B_)   // 1024

// Device-global accumulators / scratch (no allocations allowed)
__device__ double g_bind;
__device__ double g_denoise;
__device__ double g_mreg;
__device__ double g_msum;
__device__ float  g_ql[B_ * NL_];
__device__ int    g_count = 0;   // self-resetting last-block counter

__device__ __forceinline__ float warp_sum(float v) {
    #pragma unroll
    for (int o = 16; o > 0; o >>= 1)
        v += __shfl_down_sync(0xffffffffu, v, o);
    return v;
}

// Single-instruction MUFU approx (flag-independent). ~2 ulp relative error;
// x12 amplification of a RELATIVE error is ~3e-6 — harmless. The bit-exact
// requirement is only on the cancelling d^2 computation, kept in _rn below.
__device__ __forceinline__ float sqrt_approx(float x) {
    float r; asm("sqrt.approx.f32 %0, %1;" : "=f"(r) : "f"(x)); return r;
}
__device__ __forceinline__ float rcp_approx(float x) {
    float r; asm("rcp.approx.f32 %0, %1;" : "=f"(r) : "f"(x)); return r;
}

// sum of squares with XLA's rounding: (x0^2 + x1^2) + x2^2, each op rounded
__device__ __forceinline__ float sumsq_xla(float x, float y, float z) {
    return __fadd_rn(__fadd_rn(__fmul_rn(x, x), __fmul_rn(y, y)), __fmul_rn(z, z));
}

// ONE block, 256 threads. Computes ligand charges, denoise/mreg/msum sums
// (written directly, no atomics), and zeroes g_bind for the bind kernel.
__global__ void __launch_bounds__(256) prep_kernel(
        const float* __restrict__ pred,
        const float* __restrict__ targ,
        const float* __restrict__ scaf,
        const float* __restrict__ lfeat,
        const float* __restrict__ mask,
        const float* __restrict__ lig_tab) {
    __shared__ float r_mse[8], r_md[8], r_m[8];
    const int tid = threadIdx.x;

    float mse_s = 0.f, md_s = 0.f, m_s = 0.f;
    #pragma unroll
    for (int i = 0; i < (B_ * NL_) / 256; i++) {
        int idx = i * 256 + tid;
        float m = mask[idx];

        const float* p = pred + idx * 3;
        const float* t = targ + idx * 3;
        const float* s = scaf + idx * 3;
        float mse = 0.f, md = 0.f;
        #pragma unroll
        for (int d = 0; d < 3; d++) {
            float dp = p[d] - t[d];
            float ds = s[d] - t[d];
            mse = fmaf(dp, dp, mse);
            md  = fmaf(ds, ds, md);
        }
        mse_s = fmaf(mse, m, mse_s);
        md_s  = fmaf(md,  m, md_s);
        m_s  += m;

        // argmax over DL features (first max wins, strict >)
        const float* f = lfeat + idx * DL_;
        int best = 0; float bv = f[0];
        #pragma unroll
        for (int j = 1; j < DL_; j++) {
            float v = f[j];
            if (v > bv) { bv = v; best = j; }
        }
        g_ql[idx] = lig_tab[best];
    }

    float a = warp_sum(mse_s), b = warp_sum(md_s), c = warp_sum(m_s);
    int wid = tid >> 5;
    if ((tid & 31) == 0) { r_mse[wid] = a; r_md[wid] = b; r_m[wid] = c; }
    __syncthreads();
    if (tid == 0) {
        double A = 0, Bv = 0, C = 0;
        #pragma unroll
        for (int w = 0; w < 8; w++) { A += (double)r_mse[w]; Bv += (double)r_md[w]; C += (double)r_m[w]; }
        g_denoise = A; g_mreg = Bv; g_msum = C;
        g_bind = 0.0;
    }
}

// grid: (NP/PPB, B) = 1024 blocks of 128 threads, 1 protein atom per thread.
// Ligand tile (x,y,z,x2 packed float4 + q) staged in shared. Last finishing
// block computes the final scalar (self-resetting counter).
__global__ void __launch_bounds__(TPB) bind_kernel(
        const float* __restrict__ x0,        // target_coords2 [B,NL,3]
        const float* __restrict__ prot,      // protein_coords [B,NP,3]
        const float* __restrict__ pfeat,     // protein_features [B,NP,DP]
        const float* __restrict__ prot_tab,  // [DP]
        float* __restrict__ out)
{
    __shared__ float4 slig[NL_];   // x, y, z, x2
    __shared__ float  sq[NL_];
    __shared__ float  sred[TPB / 32];

    const int b   = blockIdx.y;
    const int tid = threadIdx.x;

    // Stage ligand tile (NL_/TPB = 2 entries per thread)
    #pragma unroll
    for (int i = tid; i < NL_; i += TPB) {
        const float* c = x0 + (b * NL_ + i) * 3;
        float x = c[0], y = c[1], z = c[2];
        slig[i] = make_float4(x, y, z, sumsq_xla(x, y, z));
        sq[i]   = g_ql[b * NL_ + i];
    }
    __syncthreads();

    const float t0 = prot_tab[0], t1 = prot_tab[1], t2 = prot_tab[2], t3 = prot_tab[3];

    const int m = blockIdx.x * PPB + tid;
    const float* c = prot + (b * NP_ + m) * 3;
    const float px = c[0], py = c[1], pz = c[2];
    const float p2 = sumsq_xla(px, py, pz);

    const float* f = pfeat + (b * NP_ + m) * DP_;
    float f0 = f[0], f1 = f[1], f2 = f[2], f3 = f[3];
    float qp = t0; float bv = f0;            // argmax over 4, first-max-wins
    if (f1 > bv) { bv = f1; qp = t1; }
    if (f2 > bv) { bv = f2; qp = t2; }
    if (f3 > bv) { bv = f3; qp = t3; }

    float e = 0.f, v = 0.f;
    #pragma unroll 8
    for (int n = 0; n < NL_; n++) {
        float4 L = slig[n];
        // === bit-match XLA fp32 sequence for the cancelling d^2 path ===
        float dot = __fmaf_rn(L.z, pz, __fmaf_rn(L.y, py, __fmul_rn(L.x, px)));
        float d2  = __fsub_rn(__fadd_rn(L.w, p2), __fmul_rn(2.0f, dot));
        d2 = fmaxf(d2, 0.0f);
        // relative-error-only path: single MUFU ops
        float d    = __fadd_rn(sqrt_approx(d2), DELTA_);
        float inv  = rcp_approx(d);
        // integer_pow(inv, 6) via repeated squaring, each mul rounded:
        float inv2 = __fmul_rn(inv,  inv);
        float inv4 = __fmul_rn(inv2, inv2);
        float inv6 = __fmul_rn(inv2, inv4);
        // vdw: round(inv6*inv6) - inv6 (NOT fused)
        v += __fsub_rn(__fmul_rn(inv6, inv6), inv6);
        e  = fmaf(sq[n], inv, e);            // elec: qp factored out (no amplification)
    }
    float acc = fmaf(qp, e, 0.f) + v;

    // block reduction -> one double atomic per block
    float ws = warp_sum(acc);
    if ((tid & 31) == 0) sred[tid >> 5] = ws;
    __syncthreads();
    if (tid == 0) {
        float blk = 0.f;
        #pragma unroll
        for (int w = 0; w < TPB / 32; w++) blk += sred[w];
        atomicAdd(&g_bind, (double)blk);
        __threadfence();
        int old = atomicAdd(&g_count, 1);
        if (old == NBLOCKS - 1) {
            g_count = 0;                     // self-reset: deterministic per launch
            __threadfence();
            // all other blocks' g_bind atomics are ordered before their
            // g_count increments; fenced volatile load sees the final value
            double bind = *((volatile double*)&g_bind);
            double msum = g_msum;
            double val = g_denoise / msum
                       + L_BIND_ * (bind / (double)B_)
                       + L_MREG_ * (g_mreg / msum);
            out[0] = (float)val;
        }
    }
}

extern "C" void kernel_launch(void* const* d_in, const int* in_sizes, int n_in,
                              void* d_out, int out_size) {
    const float* pred     = (const float*)d_in[0];  // predicted_noise   [B,NL,3]
    const float* targ     = (const float*)d_in[1];  // target_coords     [B,NL,3]
    const float* scaf     = (const float*)d_in[2];  // scaffold_coords   [B,NL,3]
    const float* x0       = (const float*)d_in[3];  // target_coords2    [B,NL,3]
    const float* lfeat    = (const float*)d_in[4];  // target_features   [B,NL,DL]
    const float* mask     = (const float*)d_in[5];  // mask              [B,NL]
    const float* prot     = (const float*)d_in[6];  // protein_coords    [B,NP,3]
    const float* pfeat    = (const float*)d_in[7];  // protein_features  [B,NP,DP]
    const float* lig_tab  = (const float*)d_in[8];  // [DL]
    const float* prot_tab = (const float*)d_in[9];  // [DP]
    float* out = (float*)d_out;

    prep_kernel<<<1, 256>>>(pred, targ, scaf, lfeat, mask, lig_tab);
    dim3 grid(NP_ / PPB, B_);
    bind_kernel<<<grid, TPB>>>(x0, prot, pfeat, prot_tab, out);
}

// round 6
// speedup vs baseline: 1.9833x; 1.1805x over previous
#include <cuda_runtime.h>

// Problem constants (match reference)
#define B_   8
#define NL_  256
#define NP_  16384
#define DL_  10
#define DP_  4
#define DELTA_ 0.01f
#define L_MREG_ 0.1

#define TPB 128                    // threads per block
#define PPB 128                    // protein atoms per block (1 per thread)
#define GRIDX (NP_ / PPB)          // 128
#define NBLOCKS (GRIDX * B_)       // 1024

// Device-global accumulators (no allocations allowed). Final block resets all
// to keep kernel_launch deterministic across graph replays.
__device__ double g_bind    = 0.0;
__device__ double g_denoise = 0.0;
__device__ double g_mreg    = 0.0;
__device__ double g_msum    = 0.0;
__device__ int    g_count   = 0;

typedef unsigned long long u64;

// ---- packed f32x2 helpers (per-lane rounding == scalar _rn) ----
__device__ __forceinline__ u64 pk2(float lo, float hi) {
    u64 r; asm("mov.b64 %0, {%1, %2};" : "=l"(r) : "f"(lo), "f"(hi)); return r;
}
__device__ __forceinline__ void up2(u64 p, float& lo, float& hi) {
    asm("mov.b64 {%0, %1}, %2;" : "=f"(lo), "=f"(hi) : "l"(p));
}
__device__ __forceinline__ u64 mul2_(u64 a, u64 b) {
    u64 r; asm("mul.rn.f32x2 %0, %1, %2;" : "=l"(r) : "l"(a), "l"(b)); return r;
}
__device__ __forceinline__ u64 add2_(u64 a, u64 b) {
    u64 r; asm("add.rn.f32x2 %0, %1, %2;" : "=l"(r) : "l"(a), "l"(b)); return r;
}
__device__ __forceinline__ u64 fma2_(u64 a, u64 b, u64 c) {
    u64 r; asm("fma.rn.f32x2 %0, %1, %2, %3;" : "=l"(r) : "l"(a), "l"(b), "l"(c)); return r;
}

// Single-instruction MUFU approx; relative error ~1e-7, x12 amplification of a
// RELATIVE error is harmless. Bit-exactness lives only in the cancelling d^2.
__device__ __forceinline__ float sqrt_approx(float x) {
    float r; asm("sqrt.approx.f32 %0, %1;" : "=f"(r) : "f"(x)); return r;
}
__device__ __forceinline__ float rcp_approx(float x) {
    float r; asm("rcp.approx.f32 %0, %1;" : "=f"(r) : "f"(x)); return r;
}

// sum of squares with XLA's rounding: (x0^2 + x1^2) + x2^2, each op rounded
__device__ __forceinline__ float sumsq_xla(float x, float y, float z) {
    return __fadd_rn(__fadd_rn(__fmul_rn(x, x), __fmul_rn(y, y)), __fmul_rn(z, z));
}

__device__ __forceinline__ float warp_sum(float v) {
    #pragma unroll
    for (int o = 16; o > 0; o >>= 1)
        v += __shfl_down_sync(0xffffffffu, v, o);
    return v;
}

// argmax over DL features (first max wins, strict >) -> charge
__device__ __forceinline__ float lig_q(const float* __restrict__ f,
                                       const float* __restrict__ tab) {
    int best = 0; float bv = f[0];
    #pragma unroll
    for (int j = 1; j < DL_; j++) {
        float v = f[j];
        if (v > bv) { bv = v; best = j; }
    }
    return tab[best];
}

// grid (GRIDX, B_) = 1024 blocks x 128 threads. Fully fused: staging computes
// ligand charges; warp 0 handles 2 denoise rows; main loop does 2 ligands per
// packed-f32x2 instruction; last-finishing block emits the final scalar.
__global__ void __launch_bounds__(TPB) fused_kernel(
        const float* __restrict__ pred,      // predicted_noise  [B,NL,3]
        const float* __restrict__ targ,      // target_coords    [B,NL,3]
        const float* __restrict__ scaf,      // scaffold_coords  [B,NL,3]
        const float* __restrict__ x0,        // target_coords2   [B,NL,3]
        const float* __restrict__ lfeat,     // target_features  [B,NL,DL]
        const float* __restrict__ mask,      // [B,NL]
        const float* __restrict__ prot,      // protein_coords   [B,NP,3]
        const float* __restrict__ pfeat,     // protein_features [B,NP,DP]
        const float* __restrict__ lig_tab,   // [DL]
        const float* __restrict__ prot_tab,  // [DP]
        float* __restrict__ out)
{
    __shared__ float4 sA[NL_ / 2];   // (-2x_2n, -2x_2n+1, -2y_2n, -2y_2n+1)
    __shared__ float4 sB[NL_ / 2];   // (-2z_2n, -2z_2n+1,  x2_2n,  x2_2n+1)
    __shared__ u64    sQ[NL_ / 2];   // (q_2n, q_2n+1)
    __shared__ float  sred[TPB / 32];

    const int b   = blockIdx.y;
    const int tid = threadIdx.x;

    // ---- stage ligand tile: one pair per thread ----
    {
        const float* c = x0 + (b * NL_ + 2 * tid) * 3;
        float xa = c[0], ya = c[1], za = c[2];
        float xb = c[3], yb = c[4], zb = c[5];
        // -2*coord is EXACT (power-of-2 scale); fma chain on -2x equals
        // -2 * (XLA's rounded dot chain) bit-for-bit.
        sA[tid] = make_float4(-2.f * xa, -2.f * xb, -2.f * ya, -2.f * yb);
        sB[tid] = make_float4(-2.f * za, -2.f * zb,
                              sumsq_xla(xa, ya, za), sumsq_xla(xb, yb, zb));
        const float* fa = lfeat + (b * NL_ + 2 * tid) * DL_;
        sQ[tid] = pk2(lig_q(fa, lig_tab), lig_q(fa + DL_, lig_tab));
    }
    __syncthreads();

    // ---- warp 0: this block's 2 denoise/mreg/msum rows (uniform spread) ----
    if (tid < 32) {
        float pm = 0.f, pd = 0.f, pk = 0.f;
        if (tid < 2) {
            int idx = (b * GRIDX + blockIdx.x) * 2 + tid;   // 0..2047
            float m = mask[idx];
            const float* p = pred + idx * 3;
            const float* t = targ + idx * 3;
            const float* s = scaf + idx * 3;
            float mse = 0.f, md = 0.f;
            #pragma unroll
            for (int d = 0; d < 3; d++) {
                float dp = p[d] - t[d];
                float ds = s[d] - t[d];
                mse = fmaf(dp, dp, mse);
                md  = fmaf(ds, ds, md);
            }
            pm = mse * m; pd = md * m; pk = m;
        }
        pm = warp_sum(pm); pd = warp_sum(pd); pk = warp_sum(pk);
        if (tid == 0) {
            atomicAdd(&g_denoise, (double)pm);
            atomicAdd(&g_mreg,    (double)pd);
            atomicAdd(&g_msum,    (double)pk);
        }
    }

    // ---- per-thread protein atom ----
    const int m = blockIdx.x * PPB + tid;
    const float* c = prot + (b * NP_ + m) * 3;
    const float px = c[0], py = c[1], pz = c[2];
    const float p2 = sumsq_xla(px, py, pz);
    const u64 pxx = pk2(px, px), pyy = pk2(py, py), pzz = pk2(pz, pz);
    const u64 p2p = pk2(p2, p2);

    const float4 pf = *(const float4*)(pfeat + (b * NP_ + m) * DP_);
    float qp = prot_tab[0]; float bv = pf.x;      // argmax over 4, first-max-wins
    { float t1 = prot_tab[1]; if (pf.y > bv) { bv = pf.y; qp = t1; } }
    { float t2 = prot_tab[2]; if (pf.z > bv) { bv = pf.z; qp = t2; } }
    { float t3 = prot_tab[3]; if (pf.w > bv) { bv = pf.w; qp = t3; } }

    u64 v6 = 0ull, v12 = 0ull, e = 0ull;   // (0.f, 0.f) packed accumulators

    #pragma unroll 8
    for (int n = 0; n < NL_ / 2; n++) {
        float4 A  = sA[n];
        float4 Bt = sB[n];
        u64 m2x = pk2(A.x,  A.y),  m2y = pk2(A.z,  A.w);
        u64 m2z = pk2(Bt.x, Bt.y), x2p = pk2(Bt.z, Bt.w);
        // -2*dot via fma chain (bit-equals -2 * XLA dot; see staging comment)
        u64 nd2 = fma2_(m2z, pzz, fma2_(m2y, pyy, mul2_(m2x, pxx)));
        // d2 = round( round(x2+p2) + (-2dot) )  == reference (x2+p2) - 2*dot
        u64 d2p = add2_(add2_(x2p, p2p), nd2);
        float d2a, d2b; up2(d2p, d2a, d2b);
        d2a = fmaxf(d2a, 0.f);
        d2b = fmaxf(d2b, 0.f);
        float da = __fadd_rn(sqrt_approx(d2a), DELTA_);
        float db = __fadd_rn(sqrt_approx(d2b), DELTA_);
        u64 inv  = pk2(rcp_approx(da), rcp_approx(db));
        u64 inv2 = mul2_(inv,  inv);
        u64 inv4 = mul2_(inv2, inv2);
        u64 inv6 = mul2_(inv2, inv4);
        u64 invc = mul2_(inv6, inv6);
        v6  = add2_(v6,  inv6);     // vdw split: sum inv6 and inv12 separately
        v12 = add2_(v12, invc);     // (reduction-order change only, no cancellation)
        e   = fma2_(sQ[n], inv, e); // elec: qp factored out
    }

    float v6a, v6b, v12a, v12b, ea, eb;
    up2(v6, v6a, v6b); up2(v12, v12a, v12b); up2(e, ea, eb);
    float acc = fmaf(qp, ea + eb, (v12a + v12b) - (v6a + v6b));

    // ---- block reduction -> one double atomic; counter -> final scalar ----
    float ws = warp_sum(acc);
    if ((tid & 31) == 0) sred[tid >> 5] = ws;
    __syncthreads();
    if (tid == 0) {
        float blk = 0.f;
        #pragma unroll
        for (int w = 0; w < TPB / 32; w++) blk += sred[w];
        atomicAdd(&g_bind, (double)blk);
        __threadfence();
        int old = atomicAdd(&g_count, 1);
        if (old == NBLOCKS - 1) {
            __threadfence();
            double bind = *(volatile double*)&g_bind;
            double den  = *(volatile double*)&g_denoise;
            double mrg  = *(volatile double*)&g_mreg;
            double msm  = *(volatile double*)&g_msum;
            out[0] = (float)(den / msm + bind / (double)B_ + L_MREG_ * (mrg / msm));
            // reset for next (graph-replayed) launch — volatile to keep order
            *(volatile double*)&g_bind    = 0.0;
            *(volatile double*)&g_denoise = 0.0;
            *(volatile double*)&g_mreg    = 0.0;
            *(volatile double*)&g_msum    = 0.0;
            *(volatile int*)&g_count      = 0;
        }
    }
}

extern "C" void kernel_launch(void* const* d_in, const int* in_sizes, int n_in,
                              void* d_out, int out_size) {
    const float* pred     = (const float*)d_in[0];
    const float* targ     = (const float*)d_in[1];
    const float* scaf     = (const float*)d_in[2];
    const float* x0       = (const float*)d_in[3];
    const float* lfeat    = (const float*)d_in[4];
    const float* mask     = (const float*)d_in[5];
    const float* prot     = (const float*)d_in[6];
    const float* pfeat    = (const float*)d_in[7];
    const float* lig_tab  = (const float*)d_in[8];
    const float* prot_tab = (const float*)d_in[9];
    float* out = (float*)d_out;

    dim3 grid(GRIDX, B_);
    fused_kernel<<<grid, TPB>>>(pred, targ, scaf, x0, lfeat, mask,
                                prot, pfeat, lig_tab, prot_tab, out);
}

// round 7
// speedup vs baseline: 2.1781x; 1.0982x over previous
#include <cuda_runtime.h>

// Problem constants (match reference)
#define B_   8
#define NL_  256
#define NP_  16384
#define DL_  10
#define DP_  4
#define DELTA_ 0.01f
#define L_MREG_ 0.1

#define TPB 128                    // threads per block
#define PPB 128                    // protein atoms per block (1 per thread)
#define NLB (NL_ / 2)              // ligands per block (z-split): 128
#define NPAIR (NLB / 2)            // packed ligand pairs per block: 64
#define GRIDX (NP_ / PPB)          // 128
#define NBLOCKS (GRIDX * B_ * 2)   // 2048

// Device-global accumulators (no allocations allowed). Final block resets all
// to keep kernel_launch deterministic across graph replays.
__device__ double g_bind    = 0.0;
__device__ double g_denoise = 0.0;
__device__ double g_mreg    = 0.0;
__device__ double g_msum    = 0.0;
__device__ int    g_count   = 0;

typedef unsigned long long u64;

// ---- packed f32x2 helpers (per-lane rounding == scalar _rn) ----
__device__ __forceinline__ u64 pk2(float lo, float hi) {
    u64 r; asm("mov.b64 %0, {%1, %2};" : "=l"(r) : "f"(lo), "f"(hi)); return r;
}
__device__ __forceinline__ void up2(u64 p, float& lo, float& hi) {
    asm("mov.b64 {%0, %1}, %2;" : "=f"(lo), "=f"(hi) : "l"(p));
}
__device__ __forceinline__ u64 mul2_(u64 a, u64 b) {
    u64 r; asm("mul.rn.f32x2 %0, %1, %2;" : "=l"(r) : "l"(a), "l"(b)); return r;
}
__device__ __forceinline__ u64 add2_(u64 a, u64 b) {
    u64 r; asm("add.rn.f32x2 %0, %1, %2;" : "=l"(r) : "l"(a), "l"(b)); return r;
}
__device__ __forceinline__ u64 fma2_(u64 a, u64 b, u64 c) {
    u64 r; asm("fma.rn.f32x2 %0, %1, %2, %3;" : "=l"(r) : "l"(a), "l"(b), "l"(c)); return r;
}

// Single-instruction MUFU approx; relative error ~1e-7, x12 amplification of a
// RELATIVE error is harmless. Bit-exactness lives only in the cancelling d^2.
__device__ __forceinline__ float sqrt_approx(float x) {
    float r; asm("sqrt.approx.f32 %0, %1;" : "=f"(r) : "f"(x)); return r;
}
__device__ __forceinline__ float rcp_approx(float x) {
    float r; asm("rcp.approx.f32 %0, %1;" : "=f"(r) : "f"(x)); return r;
}

// sum of squares with XLA's rounding: (x0^2 + x1^2) + x2^2, each op rounded
__device__ __forceinline__ float sumsq_xla(float x, float y, float z) {
    return __fadd_rn(__fadd_rn(__fmul_rn(x, x), __fmul_rn(y, y)), __fmul_rn(z, z));
}

__device__ __forceinline__ float warp_sum(float v) {
    #pragma unroll
    for (int o = 16; o > 0; o >>= 1)
        v += __shfl_down_sync(0xffffffffu, v, o);
    return v;
}

// argmax over DL features (first max wins, strict >) -> charge
__device__ __forceinline__ float lig_q(const float* __restrict__ f,
                                       const float* __restrict__ tab) {
    int best = 0; float bv = f[0];
    #pragma unroll
    for (int j = 1; j < DL_; j++) {
        float v = f[j];
        if (v > bv) { bv = v; best = j; }
    }
    return tab[best];
}

// grid (GRIDX, B_, 2) = 2048 blocks x 128 threads. z splits the ligand dim so
// the machine has ~14 blocks/SM resident (latency hiding). Shared tile is
// pre-packed u64 pairs -> zero repack MOVs in the hot loop. Last-finishing
// block emits the final scalar and resets globals.
__global__ void __launch_bounds__(TPB) fused_kernel(
        const float* __restrict__ pred,      // predicted_noise  [B,NL,3]
        const float* __restrict__ targ,      // target_coords    [B,NL,3]
        const float* __restrict__ scaf,      // scaffold_coords  [B,NL,3]
        const float* __restrict__ x0,        // target_coords2   [B,NL,3]
        const float* __restrict__ lfeat,     // target_features  [B,NL,DL]
        const float* __restrict__ mask,      // [B,NL]
        const float* __restrict__ prot,      // protein_coords   [B,NP,3]
        const float* __restrict__ pfeat,     // protein_features [B,NP,DP]
        const float* __restrict__ lig_tab,   // [DL]
        const float* __restrict__ prot_tab,  // [DP]
        float* __restrict__ out)
{
    __shared__ ulonglong2 sAB[NPAIR];  // (m2x pair, m2y pair)
    __shared__ ulonglong2 sCD[NPAIR];  // (m2z pair, x2  pair)
    __shared__ u64        sQ[NPAIR];   // (q, q')
    __shared__ float      sred[TPB / 32];

    const int b    = blockIdx.y;
    const int zh   = blockIdx.z;             // ligand half: 0 or 1
    const int tid  = threadIdx.x;
    const int lig0 = zh * NLB;               // first ligand of this block

    // ---- stage ligand tile: threads 0..NPAIR-1 stage one pair each ----
    if (tid < NPAIR) {
        const int li = b * NL_ + lig0 + 2 * tid;
        const float* c = x0 + li * 3;
        float xa = c[0], ya = c[1], za = c[2];
        float xb = c[3], yb = c[4], zb = c[5];
        // -2*coord is EXACT (power-of-2 scale); fma chain on -2x equals
        // -2 * (XLA's rounded dot chain) bit-for-bit.
        sAB[tid] = make_ulonglong2(pk2(-2.f * xa, -2.f * xb),
                                   pk2(-2.f * ya, -2.f * yb));
        sCD[tid] = make_ulonglong2(pk2(-2.f * za, -2.f * zb),
                                   pk2(sumsq_xla(xa, ya, za),
                                       sumsq_xla(xb, yb, zb)));
        const float* fa = lfeat + li * DL_;
        sQ[tid] = pk2(lig_q(fa, lig_tab), lig_q(fa + DL_, lig_tab));
    }
    __syncthreads();

    // ---- warp 0: this block's single denoise/mreg/msum row ----
    if (tid < 32) {
        float pm = 0.f, pd = 0.f, pk = 0.f;
        if (tid == 0) {
            int idx = (b * GRIDX + blockIdx.x) * 2 + zh;     // 0..2047
            float m = mask[idx];
            const float* p = pred + idx * 3;
            const float* t = targ + idx * 3;
            const float* s = scaf + idx * 3;
            float mse = 0.f, md = 0.f;
            #pragma unroll
            for (int d = 0; d < 3; d++) {
                float dp = p[d] - t[d];
                float ds = s[d] - t[d];
                mse = fmaf(dp, dp, mse);
                md  = fmaf(ds, ds, md);
            }
            pm = mse * m; pd = md * m; pk = m;
            atomicAdd(&g_denoise, (double)pm);
            atomicAdd(&g_mreg,    (double)pd);
            atomicAdd(&g_msum,    (double)pk);
        }
    }

    // ---- per-thread protein atom ----
    const int m = blockIdx.x * PPB + tid;
    const float* c = prot + (b * NP_ + m) * 3;
    const float px = c[0], py = c[1], pz = c[2];
    const float p2 = sumsq_xla(px, py, pz);
    const u64 pxx = pk2(px, px), pyy = pk2(py, py), pzz = pk2(pz, pz);
    const u64 p2p = pk2(p2, p2);

    const float4 pf = *(const float4*)(pfeat + (b * NP_ + m) * DP_);
    float qp = prot_tab[0]; float bv = pf.x;      // argmax over 4, first-max-wins
    { float t1 = prot_tab[1]; if (pf.y > bv) { bv = pf.y; qp = t1; } }
    { float t2 = prot_tab[2]; if (pf.z > bv) { bv = pf.z; qp = t2; } }
    { float t3 = prot_tab[3]; if (pf.w > bv) { bv = pf.w; qp = t3; } }

    u64 v6 = 0ull, v12 = 0ull, e = 0ull;   // (0.f, 0.f) packed accumulators

    #pragma unroll 8
    for (int n = 0; n < NPAIR; n++) {
        ulonglong2 AB = sAB[n];      // LDS.128 -> two u64 reg pairs, no movs
        ulonglong2 CD = sCD[n];
        // -2*dot via fma chain (bit-equals -2 * XLA dot; see staging comment)
        u64 nd2 = fma2_(CD.x, pzz, fma2_(AB.y, pyy, mul2_(AB.x, pxx)));
        // d2 = round( round(x2+p2) + (-2dot) )  == reference (x2+p2) - 2*dot
        u64 d2p = add2_(add2_(CD.y, p2p), nd2);
        float d2a, d2b; up2(d2p, d2a, d2b);
        d2a = fmaxf(d2a, 0.f);
        d2b = fmaxf(d2b, 0.f);
        float da = __fadd_rn(sqrt_approx(d2a), DELTA_);
        float db = __fadd_rn(sqrt_approx(d2b), DELTA_);
        u64 inv  = pk2(rcp_approx(da), rcp_approx(db));
        u64 inv2 = mul2_(inv,  inv);
        u64 inv4 = mul2_(inv2, inv2);
        u64 inv6 = mul2_(inv2, inv4);
        u64 invc = mul2_(inv6, inv6);
        v6  = add2_(v6,  inv6);     // vdw split: sum inv6 and inv12 separately
        v12 = add2_(v12, invc);     // (reduction-order change only, no cancellation)
        e   = fma2_(sQ[n], inv, e); // elec: qp factored out
    }

    float v6a, v6b, v12a, v12b, ea, eb;
    up2(v6, v6a, v6b); up2(v12, v12a, v12b); up2(e, ea, eb);
    float acc = fmaf(qp, ea + eb, (v12a + v12b) - (v6a + v6b));

    // ---- block reduction -> one double atomic; counter -> final scalar ----
    float ws = warp_sum(acc);
    if ((tid & 31) == 0) sred[tid >> 5] = ws;
    __syncthreads();
    if (tid == 0) {
        float blk = 0.f;
        #pragma unroll
        for (int w = 0; w < TPB / 32; w++) blk += sred[w];
        atomicAdd(&g_bind, (double)blk);
        __threadfence();
        int old = atomicAdd(&g_count, 1);
        if (old == NBLOCKS - 1) {
            __threadfence();
            double bind = *(volatile double*)&g_bind;
            double den  = *(volatile double*)&g_denoise;
            double mrg  = *(volatile double*)&g_mreg;
            double msm  = *(volatile double*)&g_msum;
            out[0] = (float)(den / msm + bind / (double)B_ + L_MREG_ * (mrg / msm));
            // reset for next (graph-replayed) launch — volatile to keep order
            *(volatile double*)&g_bind    = 0.0;
            *(volatile double*)&g_denoise = 0.0;
            *(volatile double*)&g_mreg    = 0.0;
            *(volatile double*)&g_msum    = 0.0;
            *(volatile int*)&g_count      = 0;
        }
    }
}

extern "C" void kernel_launch(void* const* d_in, const int* in_sizes, int n_in,
                              void* d_out, int out_size) {
    const float* pred     = (const float*)d_in[0];
    const float* targ     = (const float*)d_in[1];
    const float* scaf     = (const float*)d_in[2];
    const float* x0       = (const float*)d_in[3];
    const float* lfeat    = (const float*)d_in[4];
    const float* mask     = (const float*)d_in[5];
    const float* prot     = (const float*)d_in[6];
    const float* pfeat    = (const float*)d_in[7];
    const float* lig_tab  = (const float*)d_in[8];
    const float* prot_tab = (const float*)d_in[9];
    float* out = (float*)d_out;

    dim3 grid(GRIDX, B_, 2);
    fused_kernel<<<grid, TPB>>>(pred, targ, scaf, x0, lfeat, mask,
                                prot, pfeat, lig_tab, prot_tab, out);
}

// round 9
// speedup vs baseline: 2.3210x; 1.0656x over previous
#include <cuda_runtime.h>

// Problem constants (match reference)
#define B_   8
#define NL_  256
#define NP_  16384
#define DL_  10
#define DP_  4
#define DELTA_ 0.01f
#define L_MREG_ 0.1

#define TPB 128                    // threads per block
#define PPT 2                      // protein atoms per thread
#define PPB (TPB * PPT)            // protein atoms per block: 256
#define NLB (NL_ / 4)              // ligands per block (z-split into 4): 64
#define NPAIR (NLB / 2)            // packed ligand pairs per block: 32
#define GRIDX (NP_ / PPB)          // 64
#define NBLOCKS (GRIDX * B_ * 4)   // 2048

// Device-global accumulators (no allocations allowed). Final block resets all
// to keep kernel_launch deterministic across graph replays.
__device__ double g_bind    = 0.0;
__device__ double g_denoise = 0.0;
__device__ double g_mreg    = 0.0;
__device__ double g_msum    = 0.0;
__device__ int    g_count   = 0;

typedef unsigned long long u64;

// ---- packed f32x2 helpers (per-lane rounding == scalar _rn) ----
__device__ __forceinline__ u64 pk2(float lo, float hi) {
    u64 r; asm("mov.b64 %0, {%1, %2};" : "=l"(r) : "f"(lo), "f"(hi)); return r;
}
__device__ __forceinline__ void up2(u64 p, float& lo, float& hi) {
    asm("mov.b64 {%0, %1}, %2;" : "=f"(lo), "=f"(hi) : "l"(p));
}
__device__ __forceinline__ u64 mul2_(u64 a, u64 b) {
    u64 r; asm("mul.rn.f32x2 %0, %1, %2;" : "=l"(r) : "l"(a), "l"(b)); return r;
}
__device__ __forceinline__ u64 add2_(u64 a, u64 b) {
    u64 r; asm("add.rn.f32x2 %0, %1, %2;" : "=l"(r) : "l"(a), "l"(b)); return r;
}
__device__ __forceinline__ u64 fma2_(u64 a, u64 b, u64 c) {
    u64 r; asm("fma.rn.f32x2 %0, %1, %2, %3;" : "=l"(r) : "l"(a), "l"(b), "l"(c)); return r;
}

// Single-instruction MUFU approx; relative error ~1e-7, x12 amplification of a
// RELATIVE error is harmless. Bit-exactness lives only in the cancelling d^2.
__device__ __forceinline__ float sqrt_approx(float x) {
    float r; asm("sqrt.approx.f32 %0, %1;" : "=f"(r) : "f"(x)); return r;
}
__device__ __forceinline__ float rcp_approx(float x) {
    float r; asm("rcp.approx.f32 %0, %1;" : "=f"(r) : "f"(x)); return r;
}

// sum of squares with XLA's rounding: (x0^2 + x1^2) + x2^2, each op rounded
__device__ __forceinline__ float sumsq_xla(float x, float y, float z) {
    return __fadd_rn(__fadd_rn(__fmul_rn(x, x), __fmul_rn(y, y)), __fmul_rn(z, z));
}

__device__ __forceinline__ float warp_sum(float v) {
    #pragma unroll
    for (int o = 16; o > 0; o >>= 1)
        v += __shfl_down_sync(0xffffffffu, v, o);
    return v;
}

// argmax over DL features (first max wins, strict >) -> charge
__device__ __forceinline__ float lig_q(const float* __restrict__ f,
                                       const float* __restrict__ tab) {
    int best = 0; float bv = f[0];
    #pragma unroll
    for (int j = 1; j < DL_; j++) {
        float v = f[j];
        if (v > bv) { bv = v; best = j; }
    }
    return tab[best];
}

// Per-protein state for the 2-proteins-per-thread mainloop.
struct Prot {
    u64 pxx, pyy, pzz, p2p;     // broadcast-packed coords / |p|^2
    u64 v6, v12, e;             // packed accumulators
    float qp;                   // protein charge (argmax of 4 features)
};

// grid (GRIDX, B_, 4) = 2048 blocks x 128 threads. Each thread processes one
// packed ligand pair against TWO protein atoms: LDS + loop overhead amortized
// x2, two independent MUFU chains per iteration for latency hiding.
__global__ void __launch_bounds__(TPB, 10) fused_kernel(
        const float* __restrict__ pred,      // predicted_noise  [B,NL,3]
        const float* __restrict__ targ,      // target_coords    [B,NL,3]
        const float* __restrict__ scaf,      // scaffold_coords  [B,NL,3]
        const float* __restrict__ x0,        // target_coords2   [B,NL,3]
        const float* __restrict__ lfeat,     // target_features  [B,NL,DL]
        const float* __restrict__ mask,      // [B,NL]
        const float* __restrict__ prot,      // protein_coords   [B,NP,3]
        const float* __restrict__ pfeat,     // protein_features [B,NP,DP]
        const float* __restrict__ lig_tab,   // [DL]
        const float* __restrict__ prot_tab,  // [DP]
        float* __restrict__ out)
{
    __shared__ ulonglong2 sAB[NPAIR];  // (m2x pair, m2y pair)
    __shared__ ulonglong2 sCD[NPAIR];  // (m2z pair, x2  pair)
    __shared__ u64        sQ[NPAIR];   // (q, q')
    __shared__ float      sred[TPB / 32];

    const int b    = blockIdx.y;
    const int zh   = blockIdx.z;             // ligand quarter: 0..3
    const int tid  = threadIdx.x;
    const int lig0 = zh * NLB;               // first ligand of this block

    // ---- stage ligand tile: threads 0..NPAIR-1 stage one pair each ----
    if (tid < NPAIR) {
        const int li = b * NL_ + lig0 + 2 * tid;
        const float* c = x0 + li * 3;
        float xa = c[0], ya = c[1], za = c[2];
        float xb = c[3], yb = c[4], zb = c[5];
        // -2*coord is EXACT (power-of-2 scale); fma chain on -2x equals
        // -2 * (XLA's rounded dot chain) bit-for-bit.
        sAB[tid] = make_ulonglong2(pk2(-2.f * xa, -2.f * xb),
                                   pk2(-2.f * ya, -2.f * yb));
        sCD[tid] = make_ulonglong2(pk2(-2.f * za, -2.f * zb),
                                   pk2(sumsq_xla(xa, ya, za),
                                       sumsq_xla(xb, yb, zb)));
        const float* fa = lfeat + li * DL_;
        sQ[tid] = pk2(lig_q(fa, lig_tab), lig_q(fa + DL_, lig_tab));
    }
    __syncthreads();

    // ---- thread 0: this block's single denoise/mreg/msum row ----
    if (tid == 0) {
        int idx = (b * GRIDX + blockIdx.x) * 4 + zh;     // 0..2047 bijection
        float m = mask[idx];
        const float* p = pred + idx * 3;
        const float* t = targ + idx * 3;
        const float* s = scaf + idx * 3;
        float mse = 0.f, md = 0.f;
        #pragma unroll
        for (int d = 0; d < 3; d++) {
            float dp = p[d] - t[d];
            float ds = s[d] - t[d];
            mse = fmaf(dp, dp, mse);
            md  = fmaf(ds, ds, md);
        }
        atomicAdd(&g_denoise, (double)(mse * m));
        atomicAdd(&g_mreg,    (double)(md  * m));
        atomicAdd(&g_msum,    (double)m);
    }

    // ---- per-thread protein atoms (2, strided by TPB for coalescing) ----
    const float t0 = prot_tab[0], t1 = prot_tab[1],
                t2 = prot_tab[2], t3 = prot_tab[3];
    Prot P[PPT];
    #pragma unroll
    for (int r = 0; r < PPT; r++) {
        const int m = blockIdx.x * PPB + r * TPB + tid;
        const float* c = prot + (b * NP_ + m) * 3;
        float px = c[0], py = c[1], pz = c[2];
        float p2 = sumsq_xla(px, py, pz);
        P[r].pxx = pk2(px, px); P[r].pyy = pk2(py, py);
        P[r].pzz = pk2(pz, pz); P[r].p2p = pk2(p2, p2);
        const float4 pf = *(const float4*)(pfeat + (b * NP_ + m) * DP_);
        float qp = t0; float bv = pf.x;      // argmax over 4, first-max-wins
        if (pf.y > bv) { bv = pf.y; qp = t1; }
        if (pf.z > bv) { bv = pf.z; qp = t2; }
        if (pf.w > bv) { bv = pf.w; qp = t3; }
        P[r].qp = qp;
        P[r].v6 = 0ull; P[r].v12 = 0ull; P[r].e = 0ull;
    }

    #pragma unroll 8
    for (int n = 0; n < NPAIR; n++) {
        ulonglong2 AB = sAB[n];      // LDS.128 -> u64 reg pairs, shared by both proteins
        ulonglong2 CD = sCD[n];
        u64 q = sQ[n];
        #pragma unroll
        for (int r = 0; r < PPT; r++) {
            // -2*dot via fma chain (bit-equals -2 * XLA dot; see staging comment)
            u64 nd2 = fma2_(CD.x, P[r].pzz,
                      fma2_(AB.y, P[r].pyy, mul2_(AB.x, P[r].pxx)));
            // d2 = round( round(x2+p2) + (-2dot) )  == reference (x2+p2) - 2*dot
            u64 d2p = add2_(add2_(CD.y, P[r].p2p), nd2);
            float d2a, d2b; up2(d2p, d2a, d2b);
            d2a = fmaxf(d2a, 0.f);
            d2b = fmaxf(d2b, 0.f);
            float da = __fadd_rn(sqrt_approx(d2a), DELTA_);
            float db = __fadd_rn(sqrt_approx(d2b), DELTA_);
            u64 inv  = pk2(rcp_approx(da), rcp_approx(db));
            u64 inv2 = mul2_(inv,  inv);
            u64 inv4 = mul2_(inv2, inv2);
            u64 inv6 = mul2_(inv2, inv4);
            u64 invc = mul2_(inv6, inv6);
            P[r].v6  = add2_(P[r].v6,  inv6);   // vdw split: inv6 / inv12 summed
            P[r].v12 = add2_(P[r].v12, invc);   //  separately (order-only change)
            P[r].e   = fma2_(q, inv, P[r].e);   // elec: qp factored out
        }
    }

    float acc = 0.f;
    #pragma unroll
    for (int r = 0; r < PPT; r++) {
        float v6a, v6b, v12a, v12b, ea, eb;
        up2(P[r].v6, v6a, v6b); up2(P[r].v12, v12a, v12b); up2(P[r].e, ea, eb);
        acc += fmaf(P[r].qp, ea + eb, (v12a + v12b) - (v6a + v6b));
    }

    // ---- block reduction -> one double atomic; counter -> final scalar ----
    float ws = warp_sum(acc);
    if ((tid & 31) == 0) sred[tid >> 5] = ws;
    __syncthreads();
    if (tid == 0) {
        float blk = 0.f;
        #pragma unroll
        for (int w = 0; w < TPB / 32; w++) blk += sred[w];
        atomicAdd(&g_bind, (double)blk);
        __threadfence();
        int old = atomicAdd(&g_count, 1);
        if (old == NBLOCKS - 1) {
            __threadfence();
            double bind = *(volatile double*)&g_bind;
            double den  = *(volatile double*)&g_denoise;
            double mrg  = *(volatile double*)&g_mreg;
            double msm  = *(volatile double*)&g_msum;
            out[0] = (float)(den / msm + bind / (double)B_ + L_MREG_ * (mrg / msm));
            // reset for next (graph-replayed) launch — volatile to keep order
            *(volatile double*)&g_bind    = 0.0;
            *(volatile double*)&g_denoise = 0.0;
            *(volatile double*)&g_mreg    = 0.0;
            *(volatile double*)&g_msum    = 0.0;
            *(volatile int*)&g_count      = 0;
        }
    }
}

extern "C" void kernel_launch(void* const* d_in, const int* in_sizes, int n_in,
                              void* d_out, int out_size) {
    const float* pred     = (const float*)d_in[0];
    const float* targ     = (const float*)d_in[1];
    const float* scaf     = (const float*)d_in[2];
    const float* x0       = (const float*)d_in[3];
    const float* lfeat    = (const float*)d_in[4];
    const float* mask     = (const float*)d_in[5];
    const float* prot     = (const float*)d_in[6];
    const float* pfeat    = (const float*)d_in[7];
    const float* lig_tab  = (const float*)d_in[8];
    const float* prot_tab = (const float*)d_in[9];
    float* out = (float*)d_out;

    dim3 grid(GRIDX, B_, 4);
    fused_kernel<<<grid, TPB>>>(pred, targ, scaf, x0, lfeat, mask,
                                prot, pfeat, lig_tab, prot_tab, out);
}